// round 9
// baseline (speedup 1.0000x reference)
#include <cuda_runtime.h>
#include <cuda_bf16.h>
#include <cstdint>

// Problem constants: B=8, S=2048, D=1024, F=64, TOPK=8
#define Dd     1024
#define Ff     64
#define FO     192              // 3*F fused outputs (top | feat | gates)
#define TMX    64               // max tokens per CTA (4 m16 tiles)
#define KC     32               // K chunk (elements)
#define NCH    (Dd / KC)        // 32
#define TOKENS 16384
#define NCTA   296              // 136 x 64 tok + 160 x 48 tok  (2 CTAs/SM, balanced pairs)
#define NT     256

#define PIT     80              // bf16 smem row pitch bytes (64B data + 16 pad)
#define ALOOF   (TMX * PIT)         // 5120 (lo offset within an Abf buffer)
#define ABF_BUF (2 * TMX * PIT)     // 10240 (hi + lo)
#define A32PIT  144                 // fp32 staging row pitch (128B data + 16)
#define S_A32   0                   // 64*144 = 9216 (single buffer)
#define S_ABF   9216                // 2 x ABF_BUF = 20480
#define S_B     (S_ABF + 2 * ABF_BUF)   // 29696
#define B_BUF   (2 * FO * PIT)          // 30720 (hi + lo)
#define B_LO    (FO * PIT)              // 15360
#define SMEMSZ  (S_B + 2 * B_BUF)       // 91136  -> 2 CTAs/SM
#define EPIP    194                 // epilogue row pitch (floats)

// Repacked weights, bf16 hi/lo split, n-major [FO][Dd]
__device__ __nv_bfloat16 g_Whi[FO * Dd];
__device__ __nv_bfloat16 g_Wlo[FO * Dd];

__device__ __forceinline__ void mma16816(float* c, const uint32_t* a,
                                         uint32_t b0, uint32_t b1) {
    asm("mma.sync.aligned.m16n8k16.row.col.f32.bf16.bf16.f32 "
        "{%0,%1,%2,%3}, {%4,%5,%6,%7}, {%8,%9}, {%0,%1,%2,%3};"
        : "+f"(c[0]), "+f"(c[1]), "+f"(c[2]), "+f"(c[3])
        : "r"(a[0]), "r"(a[1]), "r"(a[2]), "r"(a[3]), "r"(b0), "r"(b1));
}
#define LDSM4(R, addr)                                                        \
    asm volatile("ldmatrix.sync.aligned.m8n8.x4.shared.b16 {%0,%1,%2,%3}, [%4];" \
                 : "=r"((R)[0]), "=r"((R)[1]), "=r"((R)[2]), "=r"((R)[3])     \
                 : "r"(addr))

__device__ __forceinline__ uint32_t s2u(const void* p) {
    uint32_t a;
    asm("{ .reg .u64 t; cvta.to.shared.u64 t, %1; cvt.u32.u64 %0, t; }"
        : "=r"(a) : "l"(p));
    return a;
}
// Split a pair of fp32 into bf16x2 hi and bf16x2 lo (residual).
__device__ __forceinline__ void split2(float2 f, uint32_t& hi, uint32_t& lo) {
    __nv_bfloat162 h2 = __float22bfloat162_rn(f);        // low = f.x, high = f.y
    uint32_t h; memcpy(&h, &h2, 4);
    float h0 = __uint_as_float(h << 16);
    float h1 = __uint_as_float(h & 0xFFFF0000u);
    __nv_bfloat162 l2 = __float22bfloat162_rn(make_float2(f.x - h0, f.y - h1));
    memcpy(&lo, &l2, 4);
    hi = h;
}

// Coalesced repack: blocks 0..127 transpose W_top/W_feat; blocks 128..383 copy W_gates.
__global__ __launch_bounds__(256)
void repack_kernel(const float* __restrict__ Wt,
                   const float* __restrict__ Wf,
                   const float* __restrict__ Wg) {
    int b = blockIdx.x;
    if (b < 128) {
        __shared__ float tile[32][33];
        int ntile = b & 3, ktile = b >> 2;
        int tx = threadIdx.x & 31, ty = threadIdx.x >> 5;  // 32 x 8
        int n0 = ntile * 32, k0 = ktile * 32;
        const float* src = (n0 < Ff) ? Wt : Wf;
        int nb = (n0 < Ff) ? n0 : (n0 - Ff);
#pragma unroll
        for (int r = 0; r < 32; r += 8)
            tile[ty + r][tx] = src[(size_t)(k0 + ty + r) * Ff + nb + tx];
        __syncthreads();
#pragma unroll
        for (int r = 0; r < 32; r += 8) {
            float w = tile[tx][ty + r];
            __nv_bfloat16 hi = __float2bfloat16_rn(w);
            float lo = w - __bfloat162float(hi);
            size_t o = (size_t)(n0 + ty + r) * Dd + k0 + tx;
            g_Whi[o] = hi;
            g_Wlo[o] = __float2bfloat16_rn(lo);
        }
    } else {
        int i = (b - 128) * 256 + threadIdx.x;   // Ff*Dd = 65536 elems
        if (i < Ff * Dd) {
            float w = Wg[i];                      // already n-major
            __nv_bfloat16 hi = __float2bfloat16_rn(w);
            float lo = w - __bfloat162float(hi);
            size_t o = (size_t)(2 * Ff) * Dd + i;
            g_Whi[o] = hi;
            g_Wlo[o] = __float2bfloat16_rn(lo);
        }
    }
}

__global__ __launch_bounds__(NT, 2)
void moe_mma_kernel(const float* __restrict__ x,
                    const float* __restrict__ b_top,
                    const float* __restrict__ b_feat,
                    const float* __restrict__ b_gates,
                    const float* __restrict__ alpha,
                    const int*   __restrict__ nump,
                    float* __restrict__ out) {
    extern __shared__ char smc[];

    const int tid  = threadIdx.x;
    const int wid  = tid >> 5;
    const int lane = tid & 31;
    const int cid  = blockIdx.x;
    const uint32_t smemBase = s2u(smc);

    // 136 CTAs x 4 m16-tiles (64 tok), 160 CTAs x 3 m16-tiles (48 tok)
    const int T    = (cid < 136) ? 4 : 3;
    const int tok0 = (cid < 136) ? cid * 64 : 136 * 64 + (cid - 136) * 48;
    const int Mloc = T * 16;

    // Warp owns n-slice of 24 cols (3 n8-tiles), ALL m-tiles
    float acc[4][3][4];
#pragma unroll
    for (int i = 0; i < 4; i++)
#pragma unroll
        for (int j = 0; j < 3; j++)
#pragma unroll
            for (int q = 0; q < 4; q++) acc[i][j][q] = 0.0f;

    // ---- cp.async loaders ----
    auto cpA = [&](int kb) {
#pragma unroll
        for (int p = 0; p < 2; p++) {
            int s   = p * NT + tid;          // 0..511
            int row = s >> 3, seg = s & 7;   // 64 rows x 8 16B-segs
            if (row < Mloc) {
                const float* src = x + (size_t)(tok0 + row) * Dd + kb + seg * 4;
                uint32_t dst = smemBase + S_A32 + row * A32PIT + seg * 16;
                asm volatile("cp.async.cg.shared.global [%0], [%1], 16;"
                             :: "r"(dst), "l"(src));
            }
        }
    };
    auto cpB = [&](int kb, int buf) {
        uint32_t bdst = smemBase + S_B + buf * B_BUF;
#pragma unroll
        for (int p = 0; p < 6; p++) {
            int u   = p * NT + tid;          // 0..1535
            int mat = (u >= 768);
            int v   = mat ? (u - 768) : u;   // 192 rows x 4 16B-segs
            int n   = v >> 2, q = v & 3;
            const __nv_bfloat16* src =
                (mat ? g_Wlo : g_Whi) + (size_t)n * Dd + kb + q * 8;
            uint32_t dst = bdst + (mat ? B_LO : 0) + n * PIT + q * 16;
            asm volatile("cp.async.cg.shared.global [%0], [%1], 16;"
                         :: "r"(dst), "l"(src));
        }
    };

    // ---- shared convert: A32 staging -> Abf[buf] bf16 hi/lo (once per chunk) ----
    auto convert = [&](int buf) {
        int row = tid >> 2, q = tid & 3;     // 8 floats per thread
        if (row < Mloc) {
            const char* src = smc + S_A32 + row * A32PIT + q * 32;
            char* dhi = smc + S_ABF + buf * ABF_BUF + row * PIT + q * 16;
            char* dlo = dhi + ALOOF;
#pragma unroll
            for (int j = 0; j < 2; j++) {
                float4 v = *(const float4*)(src + j * 16);
                uint32_t h0, l0, h1, l1;
                split2(make_float2(v.x, v.y), h0, l0);
                split2(make_float2(v.z, v.w), h1, l1);
                *(uint2*)(dhi + j * 8) = make_uint2(h0, h1);
                *(uint2*)(dlo + j * 8) = make_uint2(l0, l1);
            }
        }
    };

    // ---- ldmatrix lane address bases ----
    const int ll = lane & 15;
    const uint32_t bLaneOff = (ll & 7) * PIT + ((ll >> 3) & 1) * 16
                            + (lane >> 4) * B_LO;   // lanes 16-31 -> lo matrix
    const uint32_t bBase0 = smemBase + S_B + (wid * 24) * PIT + bLaneOff;
    const uint32_t aLaneOff =
        ((lane & 7) + ((lane >> 3) & 1) * 8) * PIT + (lane >> 4) * 16;
    const uint32_t aBase0 = smemBase + S_ABF + aLaneOff;

    auto domma = [&](int buf) {
        uint32_t A0 = aBase0 + buf * ABF_BUF;
        uint32_t B0 = bBase0 + buf * B_BUF;
#pragma unroll
        for (int ks = 0; ks < 2; ks++) {
            uint32_t bf[3][4];
#pragma unroll
            for (int j = 0; j < 3; j++)
                LDSM4(bf[j], B0 + j * 8 * PIT + ks * 32);
            uint32_t ah[4][4], al[4][4];
#pragma unroll
            for (int i = 0; i < 4; i++)
                if (i < T) {
                    LDSM4(ah[i], A0 + i * 16 * PIT + ks * 32);
                    LDSM4(al[i], A0 + ALOOF + i * 16 * PIT + ks * 32);
                }
            // term 1: Ah * Bh
#pragma unroll
            for (int i = 0; i < 4; i++)
                if (i < T)
#pragma unroll
                    for (int j = 0; j < 3; j++)
                        mma16816(acc[i][j], ah[i], bf[j][0], bf[j][1]);
            // term 2: Al * Bh
#pragma unroll
            for (int i = 0; i < 4; i++)
                if (i < T)
#pragma unroll
                    for (int j = 0; j < 3; j++)
                        mma16816(acc[i][j], al[i], bf[j][0], bf[j][1]);
            // term 3: Ah * Bl
#pragma unroll
            for (int i = 0; i < 4; i++)
                if (i < T)
#pragma unroll
                    for (int j = 0; j < 3; j++)
                        mma16816(acc[i][j], ah[i], bf[j][2], bf[j][3]);
        }
    };

    // ---- prologue: chunk 0 resident + chunk 1 in flight ----
    cpA(0); cpB(0, 0);
    asm volatile("cp.async.commit_group;");
    asm volatile("cp.async.wait_group 0;" ::: "memory");
    __syncthreads();
    convert(0);
    __syncthreads();
    cpA(KC); cpB(KC, 1);
    asm volatile("cp.async.commit_group;");

    // ---- mainloop ----
    for (int ch = 0; ch < NCH; ch++) {
        const int buf = ch & 1;
        domma(buf);
        if (ch + 1 < NCH) {
            asm volatile("cp.async.wait_group 0;" ::: "memory");
            __syncthreads();                  // A32(ch+1)/B(ch+1) visible to all
            convert(buf ^ 1);
        }
        __syncthreads();                      // converts visible; buffers reusable
        if (ch + 2 < NCH) {
            cpA((ch + 2) * KC); cpB((ch + 2) * KC, buf);
            asm volatile("cp.async.commit_group;");
        }
    }

    // ---- dump accumulators to epilogue smem [TMX][EPIP] ----
    float* epi = (float*)smc;
#pragma unroll
    for (int i = 0; i < 4; i++)
        if (i < T)
#pragma unroll
            for (int j = 0; j < 3; j++) {
                int r = i * 16 + (lane >> 2);
                int c = wid * 24 + j * 8 + (lane & 3) * 2;
                *(float2*)(epi + (size_t)r * EPIP + c) =
                    make_float2(acc[i][j][0], acc[i][j][1]);
                *(float2*)(epi + (size_t)(r + 8) * EPIP + c) =
                    make_float2(acc[i][j][2], acc[i][j][3]);
            }
    __syncthreads();

    // ---- per-token epilogue (one thread per token) ----
    if (tid < Mloc) {
        float* r = epi + (size_t)tid * EPIP;

        const float av = alpha[0];
        const float a  = 1.0f / (1.0f + __expf(-av));
        int num = nump ? *nump : 8;
        if (num < 1)  num = 1;
        if (num > Ff) num = Ff;

        for (int f = 0; f < Ff; ++f) {
            r[f]          += b_top[f];
            r[Ff + f]     += b_feat[f];
            float g = r[2 * Ff + f] + b_gates[f];
            r[2 * Ff + f] = 1.0f / (1.0f + __expf(-g));
        }

        // dense branch: softmax(feat) . gates
        float m2 = -3.4e38f;
        for (int f = 0; f < Ff; ++f) m2 = fmaxf(m2, r[Ff + f]);
        float s2 = 0.0f, ds = 0.0f;
        for (int f = 0; f < Ff; ++f) {
            float e = __expf(r[Ff + f] - m2);
            s2 += e;
            ds += e * r[2 * Ff + f];
        }
        float dense = ds / s2;

        // top-k branch: streaming selection + softmax over selected
        float v0 = 0.0f, se = 0.0f, ta = 0.0f;
        for (int t = 0; t < num; ++t) {
            float best = -3.4e38f; int bi = 0;
            for (int f = 0; f < Ff; ++f) {
                float v = r[f];
                if (v > best) { best = v; bi = f; }
            }
            if (t == 0) v0 = best;
            float e = __expf(best - v0);
            se += e;
            ta += e * r[2 * Ff + bi];
            r[bi] = -3.4e38f;
        }
        float topp = ta / se;

        out[tok0 + tid] = a * topp + (1.0f - a) * dense;
    }
}

extern "C" void kernel_launch(void* const* d_in, const int* in_sizes, int n_in,
                              void* d_out, int out_size) {
    const float* x   = (const float*)d_in[0];
    const float* Wt  = (const float*)d_in[1];
    const float* bt  = (const float*)d_in[2];
    const float* Wf  = (const float*)d_in[3];
    const float* bfi = (const float*)d_in[4];
    const float* Wg  = (const float*)d_in[5];
    const float* bg  = (const float*)d_in[6];
    const float* al  = (const float*)d_in[7];
    const int*   nm  = (n_in > 8) ? (const int*)d_in[8] : nullptr;
    float* out = (float*)d_out;

    repack_kernel<<<384, 256>>>(Wt, Wf, Wg);

    cudaFuncSetAttribute(moe_mma_kernel,
                         cudaFuncAttributeMaxDynamicSharedMemorySize, SMEMSZ);
    moe_mma_kernel<<<NCTA, NT, SMEMSZ>>>(x, bt, bfi, bg, al, nm, out);
}

// round 11
// speedup vs baseline: 1.0808x; 1.0808x over previous
#include <cuda_runtime.h>
#include <cuda_fp16.h>
#include <cstdint>

// Problem constants: B=8, S=2048, D=1024, F=64, TOPK=8
#define Dd     1024
#define Ff     64
#define FO     192            // 3*F fused outputs (top | feat | gates)
#define TMX    112            // max tokens per CTA (7 m16 tiles)
#define KC     64             // K chunk (elements)
#define NCH    (Dd / KC)      // 16
#define TOKENS 16384
#define NCTA   148            // 136 CTAs x 112 tokens + 12 CTAs x 96 tokens
#define NT     384
#define PIT32  288            // A fp32 smem row pitch bytes (256 + 32)
#define PIT    144            // B fp16 smem row pitch bytes (128 + 16)
#define ABUF32 (TMX * PIT32)      // 32256 B (A fp32)
#define BBUF   (2 * FO * PIT)     // 55296 B (B hi + B lo)
#define BUFSZ  (ABUF32 + BBUF)    // 87552 B
#define SMEMSZ (2 * BUFSZ)        // 175104 B (double buffered; epi overlays)
#define EPIP   194                // epilogue row pitch (floats)

// Repacked weights, fp16 hi/lo split, n-major [FO][Dd]
__device__ __half g_Whi[FO * Dd];
__device__ __half g_Wlo[FO * Dd];

__device__ __forceinline__ void mma16816(float* c, const uint32_t* a,
                                         uint32_t b0, uint32_t b1) {
    asm("mma.sync.aligned.m16n8k16.row.col.f32.f16.f16.f32 "
        "{%0,%1,%2,%3}, {%4,%5,%6,%7}, {%8,%9}, {%0,%1,%2,%3};"
        : "+f"(c[0]), "+f"(c[1]), "+f"(c[2]), "+f"(c[3])
        : "r"(a[0]), "r"(a[1]), "r"(a[2]), "r"(a[3]), "r"(b0), "r"(b1));
}
#define LDSM4(R, addr)                                                        \
    asm volatile("ldmatrix.sync.aligned.m8n8.x4.shared.b16 {%0,%1,%2,%3}, [%4];" \
                 : "=r"((R)[0]), "=r"((R)[1]), "=r"((R)[2]), "=r"((R)[3])     \
                 : "r"(addr))

__device__ __forceinline__ uint32_t s2u(const void* p) {
    uint32_t a;
    asm("{ .reg .u64 t; cvta.to.shared.u64 t, %1; cvt.u32.u64 %0, t; }"
        : "=r"(a) : "l"(p));
    return a;
}
// Pack a pair of fp32 into fp16x2 (round-to-nearest).
__device__ __forceinline__ uint32_t pkh2(float2 f) {
    __half2 h = __float22half2_rn(f);
    uint32_t u; memcpy(&u, &h, 4); return u;
}
// fp16x2 hi + residual lo from an fp32 pair.
__device__ __forceinline__ void splith(float2 f, uint32_t& hi, uint32_t& lo) {
    __half2 h = __float22half2_rn(f);
    uint32_t u; memcpy(&u, &h, 4);
    float2 hf = __half22float2(h);
    __half2 l = __float22half2_rn(make_float2(f.x - hf.x, f.y - hf.y));
    memcpy(&lo, &l, 4);
    hi = u;
}

// Coalesced repack: blocks 0..127 transpose W_top/W_feat tiles; blocks 128..383 copy W_gates.
__global__ __launch_bounds__(256)
void repack_kernel(const float* __restrict__ Wt,
                   const float* __restrict__ Wf,
                   const float* __restrict__ Wg) {
    int b = blockIdx.x;
    if (b < 128) {
        __shared__ float tile[32][33];
        int ntile = b & 3, ktile = b >> 2;
        int tx = threadIdx.x & 31, ty = threadIdx.x >> 5;  // 32 x 8
        int n0 = ntile * 32, k0 = ktile * 32;
        const float* src = (n0 < Ff) ? Wt : Wf;
        int nb = (n0 < Ff) ? n0 : (n0 - Ff);
#pragma unroll
        for (int r = 0; r < 32; r += 8)
            tile[ty + r][tx] = src[(size_t)(k0 + ty + r) * Ff + nb + tx];
        __syncthreads();
#pragma unroll
        for (int r = 0; r < 32; r += 8) {
            float w = tile[tx][ty + r];
            __half hi = __float2half_rn(w);
            float lo = w - __half2float(hi);
            size_t o = (size_t)(n0 + ty + r) * Dd + k0 + tx;
            g_Whi[o] = hi;
            g_Wlo[o] = __float2half_rn(lo);
        }
    } else {
        int i = (b - 128) * 256 + threadIdx.x;   // Ff*Dd = 65536 elems
        if (i < Ff * Dd) {
            float w = Wg[i];                      // already n-major
            __half hi = __float2half_rn(w);
            float lo = w - __half2float(hi);
            size_t o = (size_t)(2 * Ff) * Dd + i;
            g_Whi[o] = hi;
            g_Wlo[o] = __float2half_rn(lo);
        }
    }
}

__global__ __launch_bounds__(NT, 1)
void moe_mma_kernel(const float* __restrict__ x,
                    const float* __restrict__ b_top,
                    const float* __restrict__ b_feat,
                    const float* __restrict__ b_gates,
                    const float* __restrict__ alpha,
                    const int*   __restrict__ nump,
                    float* __restrict__ out) {
    extern __shared__ char smc[];

    const int tid  = threadIdx.x;
    const int wid  = tid >> 5;
    const int lane = tid & 31;
    const int cid  = blockIdx.x;
    const uint32_t smemBase = s2u(smc);

    // Work distribution: 136 CTAs x 7 m16-tiles, 12 CTAs x 6 m16-tiles
    const int  T    = (cid < 136) ? 7 : 6;
    const int  tok0 = (cid < 136) ? cid * 112 : 136 * 112 + (cid - 136) * 96;
    const int  Mloc = T * 16;
    const bool t7   = (T == 7);

    // Warp owns n8-tiles {wid, wid+12}; tiles < 8 are "top" (3-term)
    const bool hasTop = (wid < 8);   // tile0 = wid is a top tile iff wid < 8

    float acc[7][2][4];
#pragma unroll
    for (int mt = 0; mt < 7; mt++)
#pragma unroll
        for (int j = 0; j < 2; j++)
#pragma unroll
            for (int q = 0; q < 4; q++) acc[mt][j][q] = 0.0f;

    // ---- A: gmem fp32 -> smem fp32 via cp.async ----
    auto cpA = [&](int kb, int buf) {
        uint32_t adst = smemBase + buf * BUFSZ;
#pragma unroll
        for (int p = 0; p < 5; p++) {
            int s = p * NT + tid;         // 0..1919 (1792 used)
            int row = s >> 4, seg = s & 15;
            if (s < 1792 && row < Mloc) {
                const float* src = x + (size_t)(tok0 + row) * Dd + kb + seg * 4;
                uint32_t dst = adst + row * PIT32 + seg * 16;
                asm volatile("cp.async.cg.shared.global [%0], [%1], 16;"
                             :: "r"(dst), "l"(src));
            }
        }
    };
    // ---- B: gmem fp16 -> smem via cp.async ----
    auto cpB = [&](int kb, int buf) {
        uint32_t bdst = smemBase + buf * BUFSZ + ABUF32;
#pragma unroll
        for (int p = 0; p < 8; p++) {
            int u   = p * NT + tid;           // 0..3071
            int mat = (u >= 1536);
            int v   = mat ? (u - 1536) : u;   // 192 rows x 8 16B-segs
            int n   = v >> 3, q = v & 7;
            const __half* src =
                (mat ? g_Wlo : g_Whi) + (size_t)n * Dd + kb + q * 8;
            uint32_t dst = bdst + (mat ? FO * PIT : 0) + n * PIT + q * 16;
            asm volatile("cp.async.cg.shared.global [%0], [%1], 16;"
                         :: "r"(dst), "l"(src));
        }
    };

    // ---- lane address bases ----
    // B ldmatrix.x4: lanes 0-15 -> hi (k0-7, k8-15), lanes 16-31 -> lo
    const int ll = lane & 15;
    const uint32_t bLaneOff = (ll & 7) * PIT + ((ll >> 3) & 1) * 16
                            + (lane >> 4) * (FO * PIT);
    const uint32_t bBase0 = smemBase + ABUF32 + (8 * wid) * PIT + bLaneOff;
    // A scalar LDS.64: row = lane>>2, k pair = (lane&3)*2
    const uint32_t aLaneOff = (lane >> 2) * PIT32 + (lane & 3) * 8;

    auto domma = [&](int buf) {
        const char* A0 = smc + buf * BUFSZ + aLaneOff;
        uint32_t    B0 = bBase0 + buf * BUFSZ;
#pragma unroll
        for (int ks = 0; ks < 4; ks++) {
            uint32_t bf0[4], bf1[4];
            LDSM4(bf0, B0 + ks * 32);                   // tile0: hi(0,1)+lo(2,3)
            LDSM4(bf1, B0 + 96 * PIT + ks * 32);        // tile1 (= tile0 + 12 n8-tiles)
            const char* Ak = A0 + ks * 64;
            uint32_t ah[7][4], al[7][4];
#pragma unroll
            for (int mt = 0; mt < 7; mt++)
                if (mt < 6 || t7) {
                    const char* base = Ak + mt * 16 * PIT32;
                    float2 p0 = *(const float2*)(base);
                    float2 p1 = *(const float2*)(base + 8 * PIT32);
                    float2 p2 = *(const float2*)(base + 32);
                    float2 p3 = *(const float2*)(base + 8 * PIT32 + 32);
                    if (hasTop) {
                        splith(p0, ah[mt][0], al[mt][0]);
                        splith(p1, ah[mt][1], al[mt][1]);
                        splith(p2, ah[mt][2], al[mt][2]);
                        splith(p3, ah[mt][3], al[mt][3]);
                    } else {
                        ah[mt][0] = pkh2(p0);
                        ah[mt][1] = pkh2(p1);
                        ah[mt][2] = pkh2(p2);
                        ah[mt][3] = pkh2(p3);
                    }
                }
            // tile0 hi
#pragma unroll
            for (int mt = 0; mt < 7; mt++)
                if (mt < 6 || t7) mma16816(acc[mt][0], ah[mt], bf0[0], bf0[1]);
            // tile1 hi
#pragma unroll
            for (int mt = 0; mt < 7; mt++)
                if (mt < 6 || t7) mma16816(acc[mt][1], ah[mt], bf1[0], bf1[1]);
            // tile0 lo
#pragma unroll
            for (int mt = 0; mt < 7; mt++)
                if (mt < 6 || t7) mma16816(acc[mt][0], ah[mt], bf0[2], bf0[3]);
            // tile1 lo
#pragma unroll
            for (int mt = 0; mt < 7; mt++)
                if (mt < 6 || t7) mma16816(acc[mt][1], ah[mt], bf1[2], bf1[3]);
            // tile0 xl correction (top tiles only)
            if (hasTop) {
#pragma unroll
                for (int mt = 0; mt < 7; mt++)
                    if (mt < 6 || t7) mma16816(acc[mt][0], al[mt], bf0[0], bf0[1]);
            }
        }
    };

    // ---- prologue ----
    cpA(0, 0); cpB(0, 0);
    asm volatile("cp.async.commit_group;");

    // ---- mainloop: 2-buffer cp.async pipeline ----
    for (int ch = 0; ch < NCH; ch++) {
        const int buf = ch & 1;
        if (ch + 1 < NCH) {
            cpA((ch + 1) * KC, buf ^ 1);
            cpB((ch + 1) * KC, buf ^ 1);
            asm volatile("cp.async.commit_group;");
            asm volatile("cp.async.wait_group 1;" ::: "memory");
        } else {
            asm volatile("cp.async.wait_group 0;" ::: "memory");
        }
        __syncthreads();
        domma(buf);
        __syncthreads();
    }

    // ---- dump accumulators to epilogue smem [TMX][EPIP] ----
    float* epi = (float*)smc;
#pragma unroll
    for (int mt = 0; mt < 7; mt++)
        if (mt < 6 || t7)
#pragma unroll
            for (int j = 0; j < 2; j++) {
                int r = mt * 16 + (lane >> 2);
                int c = 8 * (wid + 12 * j) + (lane & 3) * 2;
                *(float2*)(epi + (size_t)r * EPIP + c) =
                    make_float2(acc[mt][j][0], acc[mt][j][1]);
                *(float2*)(epi + (size_t)(r + 8) * EPIP + c) =
                    make_float2(acc[mt][j][2], acc[mt][j][3]);
            }
    __syncthreads();

    // ---- per-token epilogue (one thread per token) ----
    if (tid < Mloc) {
        float* r = epi + (size_t)tid * EPIP;

        const float av = alpha[0];
        const float a  = 1.0f / (1.0f + __expf(-av));
        int num = nump ? *nump : 8;
        if (num < 1)  num = 1;
        if (num > Ff) num = Ff;

        for (int f = 0; f < Ff; ++f) {
            r[f]          += b_top[f];
            r[Ff + f]     += b_feat[f];
            float g = r[2 * Ff + f] + b_gates[f];
            r[2 * Ff + f] = 1.0f / (1.0f + __expf(-g));
        }

        // dense branch: softmax(feat) . gates
        float m2 = -3.4e38f;
        for (int f = 0; f < Ff; ++f) m2 = fmaxf(m2, r[Ff + f]);
        float s2 = 0.0f, ds = 0.0f;
        for (int f = 0; f < Ff; ++f) {
            float e = __expf(r[Ff + f] - m2);
            s2 += e;
            ds += e * r[2 * Ff + f];
        }
        float dense = ds / s2;

        // top-k branch: streaming selection + softmax over selected
        float v0 = 0.0f, se = 0.0f, ta = 0.0f;
        for (int t = 0; t < num; ++t) {
            float best = -3.4e38f; int bi = 0;
            for (int f = 0; f < Ff; ++f) {
                float v = r[f];
                if (v > best) { best = v; bi = f; }
            }
            if (t == 0) v0 = best;
            float e = __expf(best - v0);
            se += e;
            ta += e * r[2 * Ff + bi];
            r[bi] = -3.4e38f;
        }
        float topp = ta / se;

        out[tok0 + tid] = a * topp + (1.0f - a) * dense;
    }
}

extern "C" void kernel_launch(void* const* d_in, const int* in_sizes, int n_in,
                              void* d_out, int out_size) {
    const float* x   = (const float*)d_in[0];
    const float* Wt  = (const float*)d_in[1];
    const float* bt  = (const float*)d_in[2];
    const float* Wf  = (const float*)d_in[3];
    const float* bfi = (const float*)d_in[4];
    const float* Wg  = (const float*)d_in[5];
    const float* bg  = (const float*)d_in[6];
    const float* al  = (const float*)d_in[7];
    const int*   nm  = (n_in > 8) ? (const int*)d_in[8] : nullptr;
    float* out = (float*)d_out;

    repack_kernel<<<384, 256>>>(Wt, Wf, Wg);

    cudaFuncSetAttribute(moe_mma_kernel,
                         cudaFuncAttributeMaxDynamicSharedMemorySize, SMEMSZ);
    moe_mma_kernel<<<NCTA, NT, SMEMSZ>>>(x, bt, bfi, bg, al, nm, out);
}

// round 12
// speedup vs baseline: 1.1019x; 1.0195x over previous
#include <cuda_runtime.h>
#include <cuda_fp16.h>
#include <cstdint>

// Problem constants: B=8, S=2048, D=1024, F=64, TOPK=8
#define Dd     1024
#define Ff     64
#define FO     192            // 3*F fused outputs (top | feat | gates)
#define TMX    112            // max tokens per CTA (7 m16 tiles)
#define KC     64             // K chunk (elements)
#define NCH    (Dd / KC)      // 16
#define TOKENS 16384
#define NCTA   148            // 136 CTAs x 112 tokens + 12 CTAs x 96 tokens
#define PIT32  288            // A fp32 smem row pitch bytes (256 + 32)
#define PIT    144            // B fp16 smem row pitch bytes (128 + 16)
#define ABUF32 (TMX * PIT32)      // 32256 B (A fp32)
#define BBUF   (2 * FO * PIT)     // 55296 B (B hi + B lo)
#define BUFSZ  (ABUF32 + BBUF)    // 87552 B
#define SMEMSZ (2 * BUFSZ)        // 175104 B (double buffered; epi overlays)
#define EPIP   194                // epilogue row pitch (floats)

// Repacked weights, fp16 hi/lo split, n-major [FO][Dd]
__device__ __half g_Whi[FO * Dd];
__device__ __half g_Wlo[FO * Dd];

__device__ __forceinline__ void mma16816(float* c, const uint32_t* a,
                                         uint32_t b0, uint32_t b1) {
    asm("mma.sync.aligned.m16n8k16.row.col.f32.f16.f16.f32 "
        "{%0,%1,%2,%3}, {%4,%5,%6,%7}, {%8,%9}, {%0,%1,%2,%3};"
        : "+f"(c[0]), "+f"(c[1]), "+f"(c[2]), "+f"(c[3])
        : "r"(a[0]), "r"(a[1]), "r"(a[2]), "r"(a[3]), "r"(b0), "r"(b1));
}
#define LDSM4(R, addr)                                                        \
    asm volatile("ldmatrix.sync.aligned.m8n8.x4.shared.b16 {%0,%1,%2,%3}, [%4];" \
                 : "=r"((R)[0]), "=r"((R)[1]), "=r"((R)[2]), "=r"((R)[3])     \
                 : "r"(addr))

__device__ __forceinline__ uint32_t s2u(const void* p) {
    uint32_t a;
    asm("{ .reg .u64 t; cvta.to.shared.u64 t, %1; cvt.u32.u64 %0, t; }"
        : "=r"(a) : "l"(p));
    return a;
}
// Pack a pair of fp32 into fp16x2 (round-to-nearest).
__device__ __forceinline__ uint32_t pkh2(float2 f) {
    __half2 h = __float22half2_rn(f);
    uint32_t u; memcpy(&u, &h, 4); return u;
}
// fp16x2 hi + residual lo from an fp32 pair.
__device__ __forceinline__ void splith(float2 f, uint32_t& hi, uint32_t& lo) {
    __half2 h = __float22half2_rn(f);
    uint32_t u; memcpy(&u, &h, 4);
    float2 hf = __half22float2(h);
    __half2 l = __float22half2_rn(make_float2(f.x - hf.x, f.y - hf.y));
    memcpy(&lo, &l, 4);
    hi = u;
}

// Coalesced repack: blocks 0..127 transpose W_top/W_feat tiles; blocks 128..383 copy W_gates.
__global__ __launch_bounds__(256)
void repack_kernel(const float* __restrict__ Wt,
                   const float* __restrict__ Wf,
                   const float* __restrict__ Wg) {
    int b = blockIdx.x;
    if (b < 128) {
        __shared__ float tile[32][33];
        int ntile = b & 3, ktile = b >> 2;
        int tx = threadIdx.x & 31, ty = threadIdx.x >> 5;  // 32 x 8
        int n0 = ntile * 32, k0 = ktile * 32;
        const float* src = (n0 < Ff) ? Wt : Wf;
        int nb = (n0 < Ff) ? n0 : (n0 - Ff);
#pragma unroll
        for (int r = 0; r < 32; r += 8)
            tile[ty + r][tx] = src[(size_t)(k0 + ty + r) * Ff + nb + tx];
        __syncthreads();
#pragma unroll
        for (int r = 0; r < 32; r += 8) {
            float w = tile[tx][ty + r];
            __half hi = __float2half_rn(w);
            float lo = w - __half2float(hi);
            size_t o = (size_t)(n0 + ty + r) * Dd + k0 + tx;
            g_Whi[o] = hi;
            g_Wlo[o] = __float2half_rn(lo);
        }
    } else {
        int i = (b - 128) * 256 + threadIdx.x;   // Ff*Dd = 65536 elems
        if (i < Ff * Dd) {
            float w = Wg[i];                      // already n-major
            __half hi = __float2half_rn(w);
            float lo = w - __half2float(hi);
            size_t o = (size_t)(2 * Ff) * Dd + i;
            g_Whi[o] = hi;
            g_Wlo[o] = __float2half_rn(lo);
        }
    }
}

__global__ __launch_bounds__(256, 1)
void moe_mma_kernel(const float* __restrict__ x,
                    const float* __restrict__ b_top,
                    const float* __restrict__ b_feat,
                    const float* __restrict__ b_gates,
                    const float* __restrict__ alpha,
                    const int*   __restrict__ nump,
                    float* __restrict__ out) {
    extern __shared__ char smc[];

    const int tid  = threadIdx.x;
    const int wid  = tid >> 5;
    const int lane = tid & 31;
    const int cid  = blockIdx.x;
    const uint32_t smemBase = s2u(smc);

    // Work distribution: 136 CTAs x 7 m16-tiles, 12 CTAs x 6 m16-tiles
    const int  T    = (cid < 136) ? 7 : 6;
    const int  tok0 = (cid < 136) ? cid * 112 : 136 * 112 + (cid - 136) * 96;
    const int  Mloc = T * 16;
    const bool t7   = (T == 7);

    // Warp owns N-slice of 24 cols (3 n8-tiles), ALL m-tiles.
    // Warps 0-2 cover cols 0-71 (entire top-logit region 0-63): 3-term.
    // Warps 3-7 cover cols 72-191 (feat/gates only): 2-term.
    const bool topw = (wid < 3);

    float acc[7][3][4];
#pragma unroll
    for (int mt = 0; mt < 7; mt++)
#pragma unroll
        for (int j = 0; j < 3; j++)
#pragma unroll
            for (int q = 0; q < 4; q++) acc[mt][j][q] = 0.0f;

    // ---- A: gmem fp32 -> smem fp32 via cp.async (7 x 16B segs/thread) ----
    auto cpA = [&](int kb, int buf) {
        uint32_t adst = smemBase + buf * BUFSZ;
#pragma unroll
        for (int p = 0; p < 7; p++) {
            int s   = p * 256 + tid;      // 0..1791
            int row = s >> 4, seg = s & 15;
            if (row < Mloc) {
                const float* src = x + (size_t)(tok0 + row) * Dd + kb + seg * 4;
                uint32_t dst = adst + row * PIT32 + seg * 16;
                asm volatile("cp.async.cg.shared.global [%0], [%1], 16;"
                             :: "r"(dst), "l"(src));
            }
        }
    };
    // ---- B: gmem fp16 -> smem via cp.async ----
    auto cpB = [&](int kb, int buf) {
        uint32_t bdst = smemBase + buf * BUFSZ + ABUF32;
#pragma unroll
        for (int p = 0; p < 12; p++) {
            int u   = p * 256 + tid;          // 0..3071
            int mat = (u >= 1536);
            int v   = mat ? (u - 1536) : u;   // 192 rows x 8 16B-segs
            int n   = v >> 3, q = v & 7;
            const __half* src =
                (mat ? g_Wlo : g_Whi) + (size_t)n * Dd + kb + q * 8;
            uint32_t dst = bdst + (mat ? FO * PIT : 0) + n * PIT + q * 16;
            asm volatile("cp.async.cg.shared.global [%0], [%1], 16;"
                         :: "r"(dst), "l"(src));
        }
    };

    // ---- lane address bases ----
    // B ldmatrix.x4: lanes 0-15 -> hi tiles (k0-7, k8-15), lanes 16-31 -> lo tiles
    const int ll = lane & 15;
    const uint32_t bLaneOff = (ll & 7) * PIT + ((ll >> 3) & 1) * 16
                            + (lane >> 4) * (FO * PIT);
    const uint32_t bBase0 = smemBase + ABUF32 + (wid * 24) * PIT + bLaneOff;
    // A scalar LDS.64: row = lane>>2, k pair = (lane&3)*2
    const uint32_t aLaneOff = (lane >> 2) * PIT32 + (lane & 3) * 8;

    auto domma = [&](int buf) {
        const char* A0 = smc + buf * BUFSZ + aLaneOff;
        uint32_t    B0 = bBase0 + buf * BUFSZ;
#pragma unroll
        for (int ks = 0; ks < 4; ks++) {
            // B fragments: one LDSM4 per n8-tile gives hi (R0,R1) + lo (R2,R3)
            uint32_t bf[3][4];
#pragma unroll
            for (int j = 0; j < 3; j++)
                LDSM4(bf[j], B0 + j * 8 * PIT + ks * 32);
            // A fragments: scalar LDS.64 + fp16 convert (hi only, or hi+lo for top warps)
            const char* Ak = A0 + ks * 64;
            uint32_t ah[7][4], al[7][4];
#pragma unroll
            for (int mt = 0; mt < 7; mt++)
                if (mt < 6 || t7) {
                    const char* base = Ak + mt * 16 * PIT32;
                    float2 p0 = *(const float2*)(base);
                    float2 p1 = *(const float2*)(base + 8 * PIT32);
                    float2 p2 = *(const float2*)(base + 32);
                    float2 p3 = *(const float2*)(base + 8 * PIT32 + 32);
                    if (topw) {
                        splith(p0, ah[mt][0], al[mt][0]);
                        splith(p1, ah[mt][1], al[mt][1]);
                        splith(p2, ah[mt][2], al[mt][2]);
                        splith(p3, ah[mt][3], al[mt][3]);
                    } else {
                        ah[mt][0] = pkh2(p0);
                        ah[mt][1] = pkh2(p1);
                        ah[mt][2] = pkh2(p2);
                        ah[mt][3] = pkh2(p3);
                    }
                }
            // term 1: xh * Wh
#pragma unroll
            for (int mt = 0; mt < 7; mt++)
                if (mt < 6 || t7)
#pragma unroll
                    for (int j = 0; j < 3; j++)
                        mma16816(acc[mt][j], ah[mt], bf[j][0], bf[j][1]);
            // term 2: xh * Wl
#pragma unroll
            for (int mt = 0; mt < 7; mt++)
                if (mt < 6 || t7)
#pragma unroll
                    for (int j = 0; j < 3; j++)
                        mma16816(acc[mt][j], ah[mt], bf[j][2], bf[j][3]);
            // term 3 (top warps only): xl * Wh
            if (topw) {
#pragma unroll
                for (int mt = 0; mt < 7; mt++)
                    if (mt < 6 || t7)
#pragma unroll
                        for (int j = 0; j < 3; j++)
                            mma16816(acc[mt][j], al[mt], bf[j][0], bf[j][1]);
            }
        }
    };

    // ---- prologue ----
    cpA(0, 0); cpB(0, 0);
    asm volatile("cp.async.commit_group;");

    // ---- mainloop: 2-buffer cp.async pipeline ----
    for (int ch = 0; ch < NCH; ch++) {
        const int buf = ch & 1;
        if (ch + 1 < NCH) {
            cpA((ch + 1) * KC, buf ^ 1);
            cpB((ch + 1) * KC, buf ^ 1);
            asm volatile("cp.async.commit_group;");
            asm volatile("cp.async.wait_group 1;" ::: "memory");
        } else {
            asm volatile("cp.async.wait_group 0;" ::: "memory");
        }
        __syncthreads();      // chunk ch resident for all warps
        domma(buf);
        __syncthreads();      // all warps done reading buf before next cp overwrites it
    }

    // ---- dump accumulators to epilogue smem [TMX][EPIP] ----
    float* epi = (float*)smc;
#pragma unroll
    for (int mt = 0; mt < 7; mt++)
        if (mt < 6 || t7)
#pragma unroll
            for (int j = 0; j < 3; j++) {
                int r = mt * 16 + (lane >> 2);
                int c = wid * 24 + j * 8 + (lane & 3) * 2;
                *(float2*)(epi + (size_t)r * EPIP + c) =
                    make_float2(acc[mt][j][0], acc[mt][j][1]);
                *(float2*)(epi + (size_t)(r + 8) * EPIP + c) =
                    make_float2(acc[mt][j][2], acc[mt][j][3]);
            }
    __syncthreads();

    // ---- per-token epilogue (one thread per token) ----
    if (tid < Mloc) {
        float* r = epi + (size_t)tid * EPIP;

        const float av = alpha[0];
        const float a  = 1.0f / (1.0f + __expf(-av));
        int num = nump ? *nump : 8;
        if (num < 1)  num = 1;
        if (num > Ff) num = Ff;

        for (int f = 0; f < Ff; ++f) {
            r[f]          += b_top[f];
            r[Ff + f]     += b_feat[f];
            float g = r[2 * Ff + f] + b_gates[f];
            r[2 * Ff + f] = 1.0f / (1.0f + __expf(-g));
        }

        // dense branch: softmax(feat) . gates
        float m2 = -3.4e38f;
        for (int f = 0; f < Ff; ++f) m2 = fmaxf(m2, r[Ff + f]);
        float s2 = 0.0f, ds = 0.0f;
        for (int f = 0; f < Ff; ++f) {
            float e = __expf(r[Ff + f] - m2);
            s2 += e;
            ds += e * r[2 * Ff + f];
        }
        float dense = ds / s2;

        // top-k branch: streaming selection + softmax over selected
        float v0 = 0.0f, se = 0.0f, ta = 0.0f;
        for (int t = 0; t < num; ++t) {
            float best = -3.4e38f; int bi = 0;
            for (int f = 0; f < Ff; ++f) {
                float v = r[f];
                if (v > best) { best = v; bi = f; }
            }
            if (t == 0) v0 = best;
            float e = __expf(best - v0);
            se += e;
            ta += e * r[2 * Ff + bi];
            r[bi] = -3.4e38f;
        }
        float topp = ta / se;

        out[tok0 + tid] = a * topp + (1.0f - a) * dense;
    }
}

extern "C" void kernel_launch(void* const* d_in, const int* in_sizes, int n_in,
                              void* d_out, int out_size) {
    const float* x   = (const float*)d_in[0];
    const float* Wt  = (const float*)d_in[1];
    const float* bt  = (const float*)d_in[2];
    const float* Wf  = (const float*)d_in[3];
    const float* bfi = (const float*)d_in[4];
    const float* Wg  = (const float*)d_in[5];
    const float* bg  = (const float*)d_in[6];
    const float* al  = (const float*)d_in[7];
    const int*   nm  = (n_in > 8) ? (const int*)d_in[8] : nullptr;
    float* out = (float*)d_out;

    repack_kernel<<<384, 256>>>(Wt, Wf, Wg);

    cudaFuncSetAttribute(moe_mma_kernel,
                         cudaFuncAttributeMaxDynamicSharedMemorySize, SMEMSZ);
    moe_mma_kernel<<<NCTA, 256, SMEMSZ>>>(x, bt, bfi, bg, al, nm, out);
}